// round 1
// baseline (speedup 1.0000x reference)
#include <cuda_runtime.h>
#include <cuda_bf16.h>
#include <cstdint>

// ---------------------------------------------------------------------------
// WaveFDTD2D: 512x512 grid, 512 timesteps, 5-point Laplacian, zero padding.
// Persistent single-kernel design: 128 CTAs co-resident, one device-wide
// barrier per timestep (monotonic atomic counter -> safe across graph replays).
// Wavefields live in padded __device__ globals (L2-resident, ~2MB total).
// ---------------------------------------------------------------------------

#define NXG     512
#define NZG     512
#define NSTEPS  512
#define NREC    128

#define PITCH   528            // floats per padded row (multiple of 16B/4)
#define ROWS    514            // 512 + 2 halo rows
#define COFF    4              // interior column offset (16B aligned)

#define NCTA    128
#define NTHR    256

__device__ __align__(16) float g_bufA[ROWS * PITCH];
__device__ __align__(16) float g_bufB[ROWS * PITCH];
__device__ unsigned long long g_bar = 0ULL;   // monotonic, never reset

static __device__ __forceinline__ void grid_barrier() {
    __syncthreads();
    if (threadIdx.x == 0) {
        __threadfence();  // release my writes to L2
        unsigned long long token = atomicAdd(&g_bar, 1ULL);
        unsigned long long target = (token / (unsigned long long)NCTA + 1ULL)
                                    * (unsigned long long)NCTA;
        unsigned long long v;
        do {
            asm volatile("ld.acquire.gpu.u64 %0, [%1];"
                         : "=l"(v) : "l"(&g_bar) : "memory");
        } while (v < target);
    }
    __syncthreads();
}

__global__ void __launch_bounds__(NTHR, 1)
wave_fdtd_kernel(const float* __restrict__ vel,
                 const float* __restrict__ source,
                 const int*   __restrict__ p_srcx,
                 const int*   __restrict__ p_srcz,
                 const int*   __restrict__ rec_x,
                 const int*   __restrict__ rec_z,
                 float*       __restrict__ out)
{
    const int tid = threadIdx.x;
    const int bid = blockIdx.x;

    const float DT2f   = 1.0e-6f;                 // (1e-3)^2
    const float INVDXZ = 1.0f / (10.0f * 10.0f);  // 1/(dx*dz)

    // ---- zero both wavefield buffers (fresh state every launch) ----
    {
        float4* a = reinterpret_cast<float4*>(g_bufA);
        float4* b = reinterpret_cast<float4*>(g_bufB);
        const int n4 = (ROWS * PITCH) / 4;
        const float4 z = make_float4(0.f, 0.f, 0.f, 0.f);
        for (int i = bid * NTHR + tid; i < n4; i += NCTA * NTHR) {
            __stcg(a + i, z);
            __stcg(b + i, z);
        }
    }

    const int sx = p_srcx[0];
    const int sz = p_srcz[0];

    // ---- thread -> cell mapping: CTA owns 4 rows, thread owns 8 z-cells ----
    const int trow = tid >> 6;            // 0..3
    const int c0   = (tid & 63) << 3;     // 0..504  (logical z of first cell)
    const int row  = bid * 4 + trow;      // logical x row 0..511
    const size_t base = (size_t)(row + 1) * PITCH + (c0 + COFF);

    // time-invariant coefficient v^2 * dt^2 for my 8 cells
    const float4 vA = *reinterpret_cast<const float4*>(vel + (size_t)row * NZG + c0);
    const float4 vB = *reinterpret_cast<const float4*>(vel + (size_t)row * NZG + c0 + 4);
    float cf[8];
    cf[0] = vA.x * vA.x * DT2f;  cf[1] = vA.y * vA.y * DT2f;
    cf[2] = vA.z * vA.z * DT2f;  cf[3] = vA.w * vA.w * DT2f;
    cf[4] = vB.x * vB.x * DT2f;  cf[5] = vB.y * vB.y * DT2f;
    cf[6] = vB.z * vB.z * DT2f;  cf[7] = vB.w * vB.w * DT2f;

    const bool has_src = (row == sx) && (sz >= c0) && (sz < c0 + 8);
    const int  src_lane = sz - c0;

    grid_barrier();   // zeroing visible everywhere

    float* srcb = g_bufB;   // current p
    float* dstb = g_bufA;   // p_old, overwritten with p_new

    for (int t = 0; t < NSTEPS; ++t) {
        const float* pc = srcb + base;

        const float4 u0 = __ldcg(reinterpret_cast<const float4*>(pc - PITCH));
        const float4 u1 = __ldcg(reinterpret_cast<const float4*>(pc - PITCH + 4));
        const float4 m0 = __ldcg(reinterpret_cast<const float4*>(pc));
        const float4 m1 = __ldcg(reinterpret_cast<const float4*>(pc + 4));
        const float4 d0 = __ldcg(reinterpret_cast<const float4*>(pc + PITCH));
        const float4 d1 = __ldcg(reinterpret_cast<const float4*>(pc + PITCH + 4));
        const float  lf = __ldcg(pc - 1);
        const float  rg = __ldcg(pc + 8);
        const float4 o0 = __ldcg(reinterpret_cast<const float4*>(dstb + base));
        const float4 o1 = __ldcg(reinterpret_cast<const float4*>(dstb + base + 4));

        float m[8]  = { m0.x, m0.y, m0.z, m0.w, m1.x, m1.y, m1.z, m1.w };
        float up[8] = { u0.x, u0.y, u0.z, u0.w, u1.x, u1.y, u1.z, u1.w };
        float dn[8] = { d0.x, d0.y, d0.z, d0.w, d1.x, d1.y, d1.z, d1.w };
        float od[8] = { o0.x, o0.y, o0.z, o0.w, o1.x, o1.y, o1.z, o1.w };

        float nw[8];
        #pragma unroll
        for (int i = 0; i < 8; ++i) {
            const float l = (i == 0) ? lf : m[i - 1];
            const float r = (i == 7) ? rg : m[i + 1];
            // match reference order: ((up+dn)+l)+r - 4p, scaled by 1/(dx*dz)
            const float lap = ((((up[i] + dn[i]) + l) + r) - 4.0f * m[i]) * INVDXZ;
            nw[i] = (2.0f * m[i] - od[i]) + cf[i] * lap;
        }
        if (has_src) {
            nw[src_lane] += __ldg(source + t) * DT2f;
        }

        __stcg(reinterpret_cast<float4*>(dstb + base),
               make_float4(nw[0], nw[1], nw[2], nw[3]));
        __stcg(reinterpret_cast<float4*>(dstb + base + 4),
               make_float4(nw[4], nw[5], nw[6], nw[7]));

        grid_barrier();   // publish p_new to all CTAs

        // CTA 0 gathers receivers for this step (safe: step t+1 writes the
        // OTHER buffer; dstb of step t isn't rewritten until after barrier t+1,
        // which requires CTA 0's arrival, i.e. after this gather).
        if (bid == 0 && tid < NREC) {
            const int rx = __ldg(rec_x + tid);
            const int rz = __ldg(rec_z + tid);
            const float v = __ldcg(dstb + (size_t)(rx + 1) * PITCH + (rz + COFF));
            out[(size_t)tid * NSTEPS + t] = v;
        }

        float* tmp = srcb; srcb = dstb; dstb = tmp;
    }
}

extern "C" void kernel_launch(void* const* d_in, const int* in_sizes, int n_in,
                              void* d_out, int out_size)
{
    const float* vel    = (const float*)d_in[0];
    const float* source = (const float*)d_in[1];
    const int*   srcx   = (const int*)d_in[2];
    const int*   srcz   = (const int*)d_in[3];
    const int*   rec_x  = (const int*)d_in[4];
    const int*   rec_z  = (const int*)d_in[5];
    float* out = (float*)d_out;

    wave_fdtd_kernel<<<NCTA, NTHR>>>(vel, source, srcx, srcz, rec_x, rec_z, out);
}

// round 2
// speedup vs baseline: 1.4925x; 1.4925x over previous
#include <cuda_runtime.h>
#include <cuda_bf16.h>
#include <cstdint>

// ---------------------------------------------------------------------------
// WaveFDTD2D with temporal blocking (K=4 steps per device-wide barrier).
// 128 persistent CTAs, each owning 4 rows. Per block of 4 steps:
//   - load p (12 ext rows) + p_old (10 ext rows) from L2-resident globals
//   - 4 stencil substeps in SMEM on a shrinking trapezoid (rows 10,8,6,4)
//   - receivers gathered from SMEM by the owning CTA every substep
//   - store p_{n+3}, p_{n+4} (own 4 rows) to ping-pong global pair
//   - ONE grid barrier (monotonic atomic counter, graph-replay safe)
// Ping-pong global buffers make a single barrier per block race-free.
// ---------------------------------------------------------------------------

#define NX      512
#define NZ      512
#define NSTEPS  512
#define NREC    128
#define KST     4
#define NBLK    (NSTEPS / KST)     // 128
#define NCTA    128
#define NTHR    256
#define RROWS   4
#define EXT     12                 // RROWS + 2*KST
#define SROW    520                // floats per SMEM row (16B-aligned stride)
#define BUF     (EXT * SROW)
#define SMEM_FLOATS (4 * BUF)      // P0,P1,P2,Coeff
#define SMEM_BYTES  (SMEM_FLOATS * 4)

__device__ __align__(16) float g_P[2][NX * NZ];
__device__ __align__(16) float g_Q[2][NX * NZ];
__device__ unsigned long long g_bar = 0ULL;   // monotonic, never reset

static __device__ __forceinline__ void grid_barrier() {
    __syncthreads();
    if (threadIdx.x == 0) {
        __threadfence();
        unsigned long long token = atomicAdd(&g_bar, 1ULL);
        unsigned long long target = (token / (unsigned long long)NCTA + 1ULL)
                                    * (unsigned long long)NCTA;
        unsigned long long v;
        do {
            asm volatile("ld.acquire.gpu.u64 %0, [%1];"
                         : "=l"(v) : "l"(&g_bar) : "memory");
        } while (v < target);
    }
    __syncthreads();
}

// One stencil substep over SMEM rows [lo,hi] (clamped to in-grid rows).
// Sl: Laplacian source field, So: pointwise old field, Sd: destination.
static __device__ __forceinline__ void substep(
    const float* __restrict__ Sl, const float* __restrict__ So,
    float* __restrict__ Sd, const float* __restrict__ Cc,
    int lo, int hi, int g0, int tx, int ty,
    int sx, int sz, const float* __restrict__ source, int t)
{
    const float INV  = 0.01f;    // 1/(dx*dz)
    const float DT2f = 1.0e-6f;  // dt^2
    int ilo = lo; { int c = 4 - g0;   if (c > ilo) ilo = c; }
    int ihi = hi; { int c = 515 - g0; if (c < ihi) ihi = c; }
    const int colbase = 4 + tx * 4;
    for (int i = ilo + ty; i <= ihi; i += 2) {
        const int base = i * SROW + colbase;
        const float4 m  = *reinterpret_cast<const float4*>(Sl + base);
        const float4 u  = *reinterpret_cast<const float4*>(Sl + base - SROW);
        const float4 d  = *reinterpret_cast<const float4*>(Sl + base + SROW);
        const float  lf = Sl[base - 1];
        const float  rg = Sl[base + 4];
        const float4 o  = *reinterpret_cast<const float4*>(So + base);
        const float4 cf = *reinterpret_cast<const float4*>(Cc + base);
        float4 nw; float lap;
        lap  = ((((u.x + d.x) + lf)  + m.y) - 4.0f * m.x) * INV;
        nw.x = (2.0f * m.x - o.x) + cf.x * lap;
        lap  = ((((u.y + d.y) + m.x) + m.z) - 4.0f * m.y) * INV;
        nw.y = (2.0f * m.y - o.y) + cf.y * lap;
        lap  = ((((u.z + d.z) + m.y) + m.w) - 4.0f * m.z) * INV;
        nw.z = (2.0f * m.z - o.z) + cf.z * lap;
        lap  = ((((u.w + d.w) + m.z) + rg)  - 4.0f * m.w) * INV;
        nw.w = (2.0f * m.w - o.w) + cf.w * lap;
        const int g = g0 - 4 + i;
        if (g == sx && (sz >> 2) == tx) {
            reinterpret_cast<float*>(&nw)[sz & 3] += __ldg(source + t) * DT2f;
        }
        *reinterpret_cast<float4*>(Sd + base) = nw;
    }
}

__global__ void __launch_bounds__(NTHR, 1)
wave_fdtd_tb_kernel(const float* __restrict__ vel,
                    const float* __restrict__ source,
                    const int*   __restrict__ p_srcx,
                    const int*   __restrict__ p_srcz,
                    const int*   __restrict__ rec_x,
                    const int*   __restrict__ rec_z,
                    float*       __restrict__ out)
{
    extern __shared__ float sm[];
    float* P0 = sm;
    float* P1 = sm + BUF;
    float* P2 = sm + 2 * BUF;
    float* Cc = sm + 3 * BUF;

    const int tid = threadIdx.x;
    const int bid = blockIdx.x;
    const int g0  = bid * RROWS;
    const int tx  = tid & 127;
    const int ty  = tid >> 7;

    const int sx = p_srcx[0];
    const int sz = p_srcz[0];

    int my_rx = -1, my_rz = 0;
    if (tid < NREC) { my_rx = __ldg(rec_x + tid); my_rz = __ldg(rec_z + tid); }

    // ---- zero all SMEM (halo rows/cols must be and stay zero) ----
    for (int i = tid; i < SMEM_FLOATS; i += NTHR) sm[i] = 0.0f;
    __syncthreads();

    // ---- coefficient v^2*dt^2 cached in SMEM (rows i=1..10, in-grid) ----
    const float DT2f = 1.0e-6f;
    for (int idx = tid; idx < 10 * 128; idx += NTHR) {
        const int r = 1 + (idx >> 7), c = idx & 127;
        const int g = g0 - 4 + r;
        if ((unsigned)g < (unsigned)NX) {
            const float4 v = __ldg(reinterpret_cast<const float4*>(
                                   vel + (size_t)g * NZ + c * 4));
            *reinterpret_cast<float4*>(Cc + r * SROW + 4 + c * 4) =
                make_float4(v.x * v.x * DT2f, v.y * v.y * DT2f,
                            v.z * v.z * DT2f, v.w * v.w * DT2f);
        }
    }

    // ---- zero global state buffers (pair 0 is read by block 0) ----
    {
        const float4 z = make_float4(0.f, 0.f, 0.f, 0.f);
        float4* p = reinterpret_cast<float4*>(g_P[0]);
        float4* q = reinterpret_cast<float4*>(g_Q[0]);
        for (int i = bid * NTHR + tid; i < NX * NZ / 4; i += NCTA * NTHR) {
            __stcg(p + i, z);
            __stcg(q + i, z);
        }
    }
    grid_barrier();

    for (int b = 0; b < NBLK; ++b) {
        const int pb = b & 1;
        const float* gp = g_P[pb];
        const float* gq = g_Q[pb];

        // ---- load p_n (rows 0..11) and p_{n-1} (rows 1..10) ----
        for (int idx = tid; idx < EXT * 128; idx += NTHR) {
            const int r = idx >> 7, c = idx & 127;
            const int g = g0 - 4 + r;
            if ((unsigned)g < (unsigned)NX)
                *reinterpret_cast<float4*>(P1 + r * SROW + 4 + c * 4) =
                    __ldcg(reinterpret_cast<const float4*>(gp + (size_t)g * NZ + c * 4));
        }
        for (int idx = tid; idx < 10 * 128; idx += NTHR) {
            const int r = 1 + (idx >> 7), c = idx & 127;
            const int g = g0 - 4 + r;
            if ((unsigned)g < (unsigned)NX)
                *reinterpret_cast<float4*>(P0 + r * SROW + 4 + c * 4) =
                    __ldcg(reinterpret_cast<const float4*>(gq + (size_t)g * NZ + c * 4));
        }
        __syncthreads();

        const int t0 = b * KST;

        // s1: p_{n+1} = f(lap P1, old P0) -> P2, rows [1,10]
        substep(P1, P0, P2, Cc, 1, 10, g0, tx, ty, sx, sz, source, t0);
        __syncthreads();
        if (my_rx >= 0 && (my_rx >> 2) == bid)
            out[(size_t)tid * NSTEPS + t0] =
                P2[(4 + (my_rx & 3)) * SROW + 4 + my_rz];

        // s2: p_{n+2} = f(lap P2, old P1) -> P0, rows [2,9]
        substep(P2, P1, P0, Cc, 2, 9, g0, tx, ty, sx, sz, source, t0 + 1);
        __syncthreads();
        if (my_rx >= 0 && (my_rx >> 2) == bid)
            out[(size_t)tid * NSTEPS + t0 + 1] =
                P0[(4 + (my_rx & 3)) * SROW + 4 + my_rz];

        // s3: p_{n+3} = f(lap P0, old P2) -> P1, rows [3,8]
        substep(P0, P2, P1, Cc, 3, 8, g0, tx, ty, sx, sz, source, t0 + 2);
        __syncthreads();
        if (my_rx >= 0 && (my_rx >> 2) == bid)
            out[(size_t)tid * NSTEPS + t0 + 2] =
                P1[(4 + (my_rx & 3)) * SROW + 4 + my_rz];

        // s4: p_{n+4} = f(lap P1, old P0) -> P2, rows [4,7] (own rows)
        substep(P1, P0, P2, Cc, 4, 7, g0, tx, ty, sx, sz, source, t0 + 3);
        __syncthreads();
        if (my_rx >= 0 && (my_rx >> 2) == bid)
            out[(size_t)tid * NSTEPS + t0 + 3] =
                P2[(4 + (my_rx & 3)) * SROW + 4 + my_rz];

        // ---- store p_{n+4} (P2) and p_{n+3} (P1), own rows, to other pair ----
        float* gpo = g_P[pb ^ 1];
        float* gqo = g_Q[pb ^ 1];
        for (int idx = tid; idx < RROWS * 128; idx += NTHR) {
            const int r = 4 + (idx >> 7), c = idx & 127;
            const int g = g0 - 4 + r;   // always in-grid
            __stcg(reinterpret_cast<float4*>(gpo + (size_t)g * NZ + c * 4),
                   *reinterpret_cast<const float4*>(P2 + r * SROW + 4 + c * 4));
            __stcg(reinterpret_cast<float4*>(gqo + (size_t)g * NZ + c * 4),
                   *reinterpret_cast<const float4*>(P1 + r * SROW + 4 + c * 4));
        }
        grid_barrier();
    }
}

extern "C" void kernel_launch(void* const* d_in, const int* in_sizes, int n_in,
                              void* d_out, int out_size)
{
    const float* vel    = (const float*)d_in[0];
    const float* source = (const float*)d_in[1];
    const int*   srcx   = (const int*)d_in[2];
    const int*   srcz   = (const int*)d_in[3];
    const int*   rec_x  = (const int*)d_in[4];
    const int*   rec_z  = (const int*)d_in[5];
    float* out = (float*)d_out;

    cudaFuncSetAttribute(wave_fdtd_tb_kernel,
                         cudaFuncAttributeMaxDynamicSharedMemorySize, SMEM_BYTES);
    wave_fdtd_tb_kernel<<<NCTA, NTHR, SMEM_BYTES>>>(
        vel, source, srcx, srcz, rec_x, rec_z, out);
}